// round 3
// baseline (speedup 1.0000x reference)
#include <cuda_runtime.h>
#include <cstddef>

// KPN per-pixel dynamic convolution, K=15.
// data:    [1, 8, 3, 96, 96]      float32
// kernels: [1, 8, 225, 3, 96, 96] float32   (tap-major: k = i*15 + j)
// out:     [1, 8, 3, 96, 96]      float32
//
// R3 design: 2 px/thread, tiny blocks (96 thr), no tap split.
// Occupancy from many resident blocks: 14 blocks/SM = 42 warps.

#define KSZ    15
#define PAD    7
#define HH     96
#define WW     96
#define CCH    3
#define TTT    8
#define TILE_H 2
#define SMEM_W 112                 // 96 + 14 halo = 110 -> 112 (16B align)
#define SMEM_H (TILE_H + KSZ - 1)  // 16
#define SLAB   (HH * WW)           // 9216
#define KSTRIDE (CCH * HH * WW)    // 27648 floats between consecutive taps
#define NTHREADS (48 * TILE_H)     // 96

__global__ __launch_bounds__(NTHREADS, 14)
void kpn_kernel(const float* __restrict__ data,
                const float* __restrict__ kernels,
                float* __restrict__ out)
{
    __shared__ float tile[SMEM_H * SMEM_W];   // 7168 B

    const int tc = blockIdx.y;             // t*3 + c, 0..23
    const int h0 = blockIdx.x * TILE_H;    // output row base
    const float* dslab = data + (size_t)tc * SLAB;

    const int tx = threadIdx.x;            // 0..47  (w / 2)
    const int ty = threadIdx.y;            // 0..1

    // ---- cooperative load of padded data tile (zero-pad OOB) ----
    const int tid = ty * 48 + tx;          // 0..95
    for (int idx = tid; idx < SMEM_H * SMEM_W; idx += NTHREADS) {
        const int r  = idx / SMEM_W;
        const int cc = idx - r * SMEM_W;
        const int gh = h0 - PAD + r;
        const int gw = cc - PAD;
        float v = 0.0f;
        if ((unsigned)gh < (unsigned)HH && (unsigned)gw < (unsigned)WW)
            v = dslab[gh * WW + gw];
        tile[idx] = v;
    }
    __syncthreads();

    // ---- each thread produces 2 consecutive w pixels ----
    const int w = tx * 2;                  // 0,2,...,94
    const int h = h0 + ty;
    const int t = tc / CCH;
    const int c = tc - t * CCH;

    // kernels[t, k, c, h, w], tap k strides by KSTRIDE
    const float* kbase = kernels
        + ((size_t)(t * (KSZ * KSZ)) * CCH + c) * SLAB
        + (size_t)h * WW + w;

    float acc0 = 0.0f, acc1 = 0.0f;

    #pragma unroll 3
    for (int i = 0; i < KSZ; i++) {
        // data row segment: smem cols w .. w+15 (taps j=0..14 for 2 outputs)
        const float* row = &tile[(ty + i) * SMEM_W + w];
        float d[16];
        #pragma unroll
        for (int v2 = 0; v2 < 8; v2++) {
            const float2 rv = *reinterpret_cast<const float2*>(row + v2 * 2);
            d[v2 * 2 + 0] = rv.x;
            d[v2 * 2 + 1] = rv.y;
        }
        const float* kp = kbase + (size_t)(i * KSZ) * KSTRIDE;

        // 15 taps in 3 batches of 5 streaming float2 loads (MLP ~5)
        #pragma unroll
        for (int b = 0; b < 3; b++) {
            float2 kv[5];
            #pragma unroll
            for (int u = 0; u < 5; u++)
                kv[u] = __ldcs(reinterpret_cast<const float2*>(
                    kp + (size_t)(b * 5 + u) * KSTRIDE));
            #pragma unroll
            for (int u = 0; u < 5; u++) {
                const int j = b * 5 + u;
                acc0 = fmaf(kv[u].x, d[j + 0], acc0);
                acc1 = fmaf(kv[u].y, d[j + 1], acc1);
            }
        }
    }

    *reinterpret_cast<float2*>(out + (size_t)tc * SLAB + (size_t)h * WW + w)
        = make_float2(acc0, acc1);
}

extern "C" void kernel_launch(void* const* d_in, const int* in_sizes, int n_in,
                              void* d_out, int out_size)
{
    // data is the small tensor (221184), kernels the big one (49766400);
    // detect by size to be robust to metadata ordering.
    const float* data;
    const float* kernels;
    if (in_sizes[0] < in_sizes[1]) {
        data    = (const float*)d_in[0];
        kernels = (const float*)d_in[1];
    } else {
        data    = (const float*)d_in[1];
        kernels = (const float*)d_in[0];
    }

    dim3 grid(HH / TILE_H, TTT * CCH);   // (48, 24) = 1152 blocks, single wave
    dim3 block(48, TILE_H);              // 96 threads
    kpn_kernel<<<grid, block>>>(data, kernels, (float*)d_out);
}

// round 4
// speedup vs baseline: 1.0674x; 1.0674x over previous
#include <cuda_runtime.h>
#include <cstddef>

// KPN per-pixel dynamic convolution, K=15.
// data:    [1, 8, 3, 96, 96]      float32
// kernels: [1, 8, 225, 3, 96, 96] float32   (tap-major: k = i*15 + j)
// out:     [1, 8, 3, 96, 96]      float32
//
// R4 design: 1 px/thread -> 221184 threads = 46.7 warps/SM in a single
// wave (grid 576 x block 384). Max total-warp concurrency; BW-bound.

#define KSZ    15
#define PAD    7
#define HH     96
#define WW     96
#define CCH    3
#define TTT    8
#define TILE_H 4
#define SMEM_W 112                 // 96 + 14 halo = 110 -> 112
#define SMEM_H (TILE_H + KSZ - 1)  // 18
#define SLAB   (HH * WW)           // 9216
#define KSTRIDE (CCH * HH * WW)    // 27648 floats between consecutive taps
#define NTHREADS (WW * TILE_H)     // 384

__global__ __launch_bounds__(NTHREADS, 4)
void kpn_kernel(const float* __restrict__ data,
                const float* __restrict__ kernels,
                float* __restrict__ out)
{
    __shared__ float tile[SMEM_H * SMEM_W];   // 8064 B

    const int tc = blockIdx.y;             // t*3 + c, 0..23
    const int h0 = blockIdx.x * TILE_H;    // output row base
    const float* dslab = data + (size_t)tc * SLAB;

    const int tx = threadIdx.x;            // 0..95  (= w)
    const int ty = threadIdx.y;            // 0..3

    // ---- cooperative load of padded data tile (zero-pad OOB) ----
    const int tid = ty * WW + tx;          // 0..383
    #pragma unroll
    for (int idx = tid; idx < SMEM_H * SMEM_W; idx += NTHREADS) {
        const int r  = idx / SMEM_W;
        const int cc = idx - r * SMEM_W;
        const int gh = h0 - PAD + r;
        const int gw = cc - PAD;
        float v = 0.0f;
        if ((unsigned)gh < (unsigned)HH && (unsigned)gw < (unsigned)WW)
            v = dslab[gh * WW + gw];
        tile[idx] = v;
    }
    __syncthreads();

    // ---- each thread produces 1 pixel ----
    const int h = h0 + ty;
    const int t = tc / CCH;
    const int c = tc - t * CCH;

    // kernels[t, k, c, h, w], tap k strides by KSTRIDE
    const float* kbase = kernels
        + ((size_t)(t * (KSZ * KSZ)) * CCH + c) * SLAB
        + (size_t)h * WW + tx;

    float acc = 0.0f;

    #pragma unroll 3
    for (int i = 0; i < KSZ; i++) {
        // data window: smem cols tx .. tx+14 (taps j=0..14)
        const float* row = &tile[(ty + i) * SMEM_W + tx];
        float d[KSZ];
        #pragma unroll
        for (int j = 0; j < KSZ; j++)
            d[j] = row[j];

        const float* kp = kbase + i * (KSZ * KSTRIDE);

        // 15 taps in 3 batches of 5 streaming loads (MLP ~5 per warp)
        #pragma unroll
        for (int b = 0; b < 3; b++) {
            float kv[5];
            #pragma unroll
            for (int u = 0; u < 5; u++)
                kv[u] = __ldcs(kp + (b * 5 + u) * KSTRIDE);
            #pragma unroll
            for (int u = 0; u < 5; u++)
                acc = fmaf(kv[u], d[b * 5 + u], acc);
        }
    }

    out[(size_t)tc * SLAB + (size_t)h * WW + tx] = acc;
}

extern "C" void kernel_launch(void* const* d_in, const int* in_sizes, int n_in,
                              void* d_out, int out_size)
{
    // data is the small tensor (221184), kernels the big one (49766400);
    // detect by size to be robust to metadata ordering.
    const float* data;
    const float* kernels;
    if (in_sizes[0] < in_sizes[1]) {
        data    = (const float*)d_in[0];
        kernels = (const float*)d_in[1];
    } else {
        data    = (const float*)d_in[1];
        kernels = (const float*)d_in[0];
    }

    dim3 grid(HH / TILE_H, TTT * CCH);   // (24, 24) = 576 blocks, single wave
    dim3 block(WW, TILE_H);              // (96, 4)  = 384 threads
    kpn_kernel<<<grid, block>>>(data, kernels, (float*)d_out);
}

// round 6
// speedup vs baseline: 1.0985x; 1.0291x over previous
#include <cuda_runtime.h>
#include <cstddef>
#include <cstdint>

// KPN per-pixel dynamic convolution, K=15.
// data:    [1, 8, 3, 96, 96]      float32
// kernels: [1, 8, 225, 3, 96, 96] float32   (tap-major: k = i*15 + j)
// out:     [1, 8, 3, 96, 96]      float32
//
// R6 = R5 resubmit (infra failure, never ran): cp.async (LDGSTS.128)
// pipeline for the 200 MB kernels stream. 25 outstanding 16B async copies
// per thread (5 groups x 5 taps) -> MLP decoupled from the register file.
// Each thread consumes only its own ring slots, so no block barrier in the
// mainloop.

#define KSZ    15
#define PAD    7
#define HH     96
#define WW     96
#define CCH    3
#define TTT    8
#define TILE_H 4
#define SMEM_W 112                 // 96 + 14 halo -> 112
#define SMEM_H (TILE_H + KSZ - 1)  // 18
#define SLAB   (HH * WW)           // 9216
#define KSTRIDE (CCH * HH * WW)    // 27648 floats between consecutive taps
#define NTH    96                  // 24 x 4 threads
#define GSIZE  5                   // taps per async group
#define NGROUPS 45                 // 225 taps / 5
#define PIPE   5                   // groups in flight
#define SLOTS  (PIPE * GSIZE)      // 25 ring slots per thread

__global__ __launch_bounds__(NTH)
void kpn_kernel(const float* __restrict__ data,
                const float* __restrict__ kernels,
                float* __restrict__ out)
{
    __shared__ float  tile[SMEM_H * SMEM_W];     // 8064 B
    __shared__ float4 ring[SLOTS * NTH];         // 38400 B (46464 total < 48K)

    const int tc = blockIdx.y;             // t*3 + c, 0..23
    const int h0 = blockIdx.x * TILE_H;
    const int tx = threadIdx.x;            // 0..23  (w/4)
    const int ty = threadIdx.y;            // 0..3
    const int tid = ty * 24 + tx;          // 0..95

    // ---- cooperative load of padded data tile (zero-pad OOB) ----
    const float* dslab = data + (size_t)tc * SLAB;
    for (int idx = tid; idx < SMEM_H * SMEM_W; idx += NTH) {
        const int r  = idx / SMEM_W;
        const int cc = idx - r * SMEM_W;
        const int gh = h0 - PAD + r;
        const int gw = cc - PAD;
        float v = 0.0f;
        if ((unsigned)gh < (unsigned)HH && (unsigned)gw < (unsigned)WW)
            v = dslab[gh * WW + gw];
        tile[idx] = v;
    }
    __syncthreads();

    const int w = tx * 4;
    const int h = h0 + ty;
    const int t = tc / CCH;
    const int c = tc - t * CCH;

    // kernels[t, k, c, h, w], tap k strides by KSTRIDE (16B-aligned: w%4==0)
    const float* kbase = kernels
        + ((size_t)(t * (KSZ * KSZ)) * CCH + c) * SLAB
        + (size_t)h * WW + w;

    const uint32_t ring_base =
        (uint32_t)__cvta_generic_to_shared(&ring[tid]);

    // Issue async group gg (5 taps, 16B each); always commit (empty groups
    // past the end keep the wait_group arithmetic uniform).
    auto issue = [&](int gg) {
        if (gg < NGROUPS) {
            const int slotg = gg % PIPE;
            #pragma unroll
            for (int u = 0; u < GSIZE; u++) {
                const int k = gg * GSIZE + u;
                const uint32_t dst =
                    ring_base + (uint32_t)((slotg * GSIZE + u) * NTH) * 16u;
                const float* src = kbase + (size_t)k * KSTRIDE;
                asm volatile("cp.async.cg.shared.global [%0], [%1], 16;\n"
                             :: "r"(dst), "l"(src) : "memory");
            }
        }
        asm volatile("cp.async.commit_group;\n" ::: "memory");
    };

    // ---- prologue: fill the pipe (25 taps outstanding) ----
    #pragma unroll
    for (int g = 0; g < PIPE; g++) issue(g);

    float acc0 = 0.0f, acc1 = 0.0f, acc2 = 0.0f, acc3 = 0.0f;

    #pragma unroll 3
    for (int i = 0; i < KSZ; i++) {
        // data row segment: smem cols w .. w+19 (taps j=0..14 for 4 outputs)
        const float* rowp = &tile[(ty + i) * SMEM_W + w];
        float d[20];
        #pragma unroll
        for (int v4 = 0; v4 < 5; v4++) {
            const float4 rv = *reinterpret_cast<const float4*>(rowp + v4 * 4);
            d[v4 * 4 + 0] = rv.x;
            d[v4 * 4 + 1] = rv.y;
            d[v4 * 4 + 2] = rv.z;
            d[v4 * 4 + 3] = rv.w;
        }
        #pragma unroll
        for (int b = 0; b < 3; b++) {
            const int g = i * 3 + b;
            // oldest group (g) must be complete; 4 newer groups may be pending
            asm volatile("cp.async.wait_group 4;\n" ::: "memory");
            const int slotg = g % PIPE;
            #pragma unroll
            for (int u = 0; u < GSIZE; u++) {
                const float4 kv = ring[(slotg * GSIZE + u) * NTH + tid];
                const int j = b * GSIZE + u;
                acc0 = fmaf(kv.x, d[j + 0], acc0);
                acc1 = fmaf(kv.y, d[j + 1], acc1);
                acc2 = fmaf(kv.z, d[j + 2], acc2);
                acc3 = fmaf(kv.w, d[j + 3], acc3);
            }
            issue(g + PIPE);
        }
    }

    *reinterpret_cast<float4*>(out + (size_t)tc * SLAB + (size_t)h * WW + w)
        = make_float4(acc0, acc1, acc2, acc3);
}

extern "C" void kernel_launch(void* const* d_in, const int* in_sizes, int n_in,
                              void* d_out, int out_size)
{
    // data is the small tensor (221184), kernels the big one (49766400);
    // detect by size to be robust to metadata ordering.
    const float* data;
    const float* kernels;
    if (in_sizes[0] < in_sizes[1]) {
        data    = (const float*)d_in[0];
        kernels = (const float*)d_in[1];
    } else {
        data    = (const float*)d_in[1];
        kernels = (const float*)d_in[0];
    }

    dim3 grid(HH / TILE_H, TTT * CCH);   // (24, 24) = 576 blocks
    dim3 block(24, TILE_H);              // 96 threads, 4 px/thread
    kpn_kernel<<<grid, block>>>(data, kernels, (float*)d_out);
}